// round 7
// baseline (speedup 1.0000x reference)
#include <cuda_runtime.h>
#include <math.h>

#define NP 128
#define ND 3
#define DIM (NP*ND)
#define FF 32
#define HH 32
#define BB 128
#define NEDGE (NP*(NP-1))   // 16256
#define NNODE (BB*NP)       // 16384
#define SBM 34              // padded Bm row stride

// scratch (static device arrays, no allocation)
__device__ float g_A [NNODE*FF];   // h_i @ W_hi + e_b1
__device__ float g_Bm[NNODE*FF];   // h_j @ W_hj

// ---- packed f32x2 helpers (FFMA2: only reachable via PTX on sm_103a) ----
#define FMA2(d,a,b,c) asm("fma.rn.f32x2 %0, %1, %2, %3;" : "=l"(d) : "l"(a), "l"(b), "l"(c))
#define ADD2(d,a,b)   asm("add.rn.f32x2 %0, %1, %2;"     : "=l"(d) : "l"(a), "l"(b))
#define MUL2(d,a,b)   asm("mul.rn.f32x2 %0, %1, %2;"     : "=l"(d) : "l"(a), "l"(b))
#define PACK2(d,lo,hi) asm("mov.b64 %0, {%1, %2};" : "=l"(d) : "f"(lo), "f"(hi))
#define UNPK2(lo,hi,s) asm("mov.b64 {%0, %1}, %2;" : "=f"(lo), "=f"(hi) : "l"(s))

typedef unsigned long long u64;

__device__ __forceinline__ float sigf(float v) {
    return __fdividef(1.0f, 1.0f + __expf(-v));
}
__device__ __forceinline__ float siluf(float v) {
    return __fdividef(v, 1.0f + __expf(-v));
}

// ---------------------------------------------------------------------------
// Kernel 0: per-node precompute A = h@W_hi + e_b1, Bm = h@W_hj
// ---------------------------------------------------------------------------
__global__ __launch_bounds__(128) void prenode_kernel(
    const float* __restrict__ h, const float* __restrict__ e_w1,
    const float* __restrict__ e_b1)
{
    int node = blockIdx.x * 4 + (threadIdx.x >> 5);
    int f    = threadIdx.x & 31;
    float hv = h[node*FF + f];
    float a  = e_b1[f];
    float bm = 0.0f;
#pragma unroll
    for (int k = 0; k < FF; k++) {
        float hk = __shfl_sync(0xffffffffu, hv, k);
        a  += hk * e_w1[k*HH + f];
        bm += hk * e_w1[(FF + k)*HH + f];
    }
    g_A [node*FF + f] = a;
    g_Bm[node*FF + f] = bm;
}

// ---------------------------------------------------------------------------
// Kernel 1: fused edge + node kernel, TWO i's per block, coord head split by
// output halves to cap live registers at ~120 (4 blocks/SM).
// ---------------------------------------------------------------------------
__global__ __launch_bounds__(128, 4) void edge_kernel(
    const float* __restrict__ x,      const float* __restrict__ d_static,
    const float* __restrict__ e_w1,   const float* __restrict__ e_w2,
    const float* __restrict__ e_b2,   const float* __restrict__ c_w1,
    const float* __restrict__ c_b1,   const float* __restrict__ c_w2,
    const float* __restrict__ a_w,    const float* __restrict__ a_b,
    const float* __restrict__ h,
    const float* __restrict__ n_w1,   const float* __restrict__ n_b1,
    const float* __restrict__ n_w2,   const float* __restrict__ n_b2,
    float* __restrict__ x_out,        float* __restrict__ h_out)
{
    __shared__ __align__(16) float s_w2[FF*HH];     // e_w2
    __shared__ __align__(16) float s_c1[FF*HH];     // c_w1
    __shared__ __align__(16) float s_misc[8*32];    // wd,wds,eb2,cb1,aw,cw2,Ai0,Ai1
    __shared__ __align__(16) float s_bm[NP*SBM];    // staged Bm rows (batch b)
    __shared__ float s_part[2][4][32];
    __shared__ float s_xp[2][4][3];
    __shared__ float s_xi[2][3];
    __shared__ float s_ab;

    const int t = threadIdx.x;
    const int b  = blockIdx.x >> 6;
    const int ip = blockIdx.x & 63;
    const int i0 = ip*2, i1 = i0+1;
    const int j = t;
    const int lane = t & 31;
    const int warp = t >> 5;

    for (int idx = t; idx < FF*HH; idx += 128) {
        s_w2[idx] = e_w2[idx];
        s_c1[idx] = c_w1[idx];
    }
    {   // coalesced stage of Bm for batch b (128 rows x 32 floats), stride SBM
        const float4* src = (const float4*)(g_Bm + b*NP*FF);
#pragma unroll
        for (int q = 0; q < 8; q++) {
            int idx = q*128 + t;
            int row = idx >> 3;
            int col = (idx & 7) * 4;
            float4 v = src[idx];
            s_bm[row*SBM + col + 0] = v.x;
            s_bm[row*SBM + col + 1] = v.y;
            s_bm[row*SBM + col + 2] = v.z;
            s_bm[row*SBM + col + 3] = v.w;
        }
    }
    if (t < 32) {
        s_misc[t        ] = e_w1[(2*FF    )*HH + t];  // w_d
        s_misc[32  + t  ] = e_w1[(2*FF + 1)*HH + t];  // w_ds
        s_misc[64  + t  ] = e_b2[t];
        s_misc[96  + t  ] = c_b1[t];
        s_misc[128 + t  ] = a_w[t];
        s_misc[160 + t  ] = c_w2[t];
        s_misc[192 + t  ] = g_A[(b*NP + i0)*FF + t];
        s_misc[224 + t  ] = g_A[(b*NP + i1)*FF + t];
    }
    if (t == 0) s_ab = a_b[0];
    if (t < 6)  s_xi[t/3][t%3] = x[b*DIM + (t < 3 ? i0 : i1)*ND + (t%3)];
    __syncthreads();

    // ---- geometry for both edges (shared x_j load) ----
    float xj0 = x[b*DIM + j*ND + 0];
    float xj1 = x[b*DIM + j*ND + 1];
    float xj2 = x[b*DIM + j*ND + 2];
    float rxa = s_xi[0][0]-xj0, rya = s_xi[0][1]-xj1, rza = s_xi[0][2]-xj2;
    float rxb = s_xi[1][0]-xj0, ryb = s_xi[1][1]-xj1, rzb = s_xi[1][2]-xj2;
    float d2a = rxa*rxa + rya*rya + rza*rza;
    float d2b = rxb*rxb + ryb*ryb + rzb*rzb;
    float da = sqrtf(d2a + 1e-6f);
    float db = sqrtf(d2b + 1e-6f);

    int ea = i0*(NP-1) + (j < i0 ? j : j-1); if (j == i0) ea = 0;
    int eb = i1*(NP-1) + (j < i1 ? j : j-1); if (j == i1) eb = 0;
    float dsa = d_static[b*NEDGE + ea];
    float dsb = d_static[b*NEDGE + eb];
    float ds2a = dsa*dsa, ds2b = dsb*dsb;

    u64 d2ap, ds2ap, d2bp, ds2bp;
    PACK2(d2ap, d2a, d2a);  PACK2(ds2ap, ds2a, ds2a);
    PACK2(d2bp, d2b, d2b);  PACK2(ds2bp, ds2b, ds2b);

    // ---- fused layer1->layer2 for both edges, weights loaded once ----
    u64 m2a[16], m2b[16];
    {
        const ulonglong2* bp = (const ulonglong2*)(s_misc + 64);
#pragma unroll
        for (int q = 0; q < 8; q++) {
            ulonglong2 v = bp[q];
            m2a[2*q] = v.x;  m2a[2*q+1] = v.y;
            m2b[2*q] = v.x;  m2b[2*q+1] = v.y;
        }
    }
    {
        const u64* Ai0p = (const u64*)(s_misc + 192);
        const u64* Ai1p = (const u64*)(s_misc + 224);
        const u64* Wd   = (const u64*)(s_misc + 0);
        const u64* Wds  = (const u64*)(s_misc + 32);
#pragma unroll 4
        for (int kp = 0; kp < 16; kp++) {
            u64 bm = *(const u64*)(s_bm + j*SBM + 2*kp);
            u64 wd = Wd[kp], ws = Wds[kp];
            u64 pa, pb;
            ADD2(pa, Ai0p[kp], bm);
            FMA2(pa, d2ap, wd, pa);
            FMA2(pa, ds2ap, ws, pa);
            ADD2(pb, Ai1p[kp], bm);
            FMA2(pb, d2bp, wd, pb);
            FMA2(pb, ds2bp, ws, pb);
            float va0, va1, vb0, vb1;
            UNPK2(va0, va1, pa);
            UNPK2(vb0, vb1, pb);
            va0 = siluf(va0); va1 = siluf(va1);
            vb0 = siluf(vb0); vb1 = siluf(vb1);
            u64 s0a, s1a, s0b, s1b;
            PACK2(s0a, va0, va0); PACK2(s1a, va1, va1);
            PACK2(s0b, vb0, vb0); PACK2(s1b, vb1, vb1);
            const ulonglong2* w0 = (const ulonglong2*)(s_w2 + (2*kp)*HH);
#pragma unroll
            for (int q = 0; q < 8; q++) {
                ulonglong2 wa = w0[q], wb = w0[q+8];
                FMA2(m2a[2*q],   s0a, wa.x, m2a[2*q]);
                FMA2(m2a[2*q+1], s0a, wa.y, m2a[2*q+1]);
                FMA2(m2a[2*q],   s1a, wb.x, m2a[2*q]);
                FMA2(m2a[2*q+1], s1a, wb.y, m2a[2*q+1]);
                FMA2(m2b[2*q],   s0b, wa.x, m2b[2*q]);
                FMA2(m2b[2*q+1], s0b, wa.y, m2b[2*q+1]);
                FMA2(m2b[2*q],   s1b, wb.x, m2b[2*q]);
                FMA2(m2b[2*q+1], s1b, wb.y, m2b[2*q+1]);
            }
        }
    }

    // ---- silu on m (kept packed) ----
#pragma unroll
    for (int q = 0; q < 16; q++) {
        float v0, v1;
        UNPK2(v0, v1, m2a[q]); v0 = siluf(v0); v1 = siluf(v1); PACK2(m2a[q], v0, v1);
        UNPK2(v0, v1, m2b[q]); v0 = siluf(v0); v1 = siluf(v1); PACK2(m2b[q], v0, v1);
    }

    // ---- attention gates (packed dot) ----
    {
        const u64* awp = (const u64*)(s_misc + 128);
        u64 ata = 0ull, atb = 0ull;
#pragma unroll
        for (int q = 0; q < 16; q++) {
            u64 w = awp[q];
            FMA2(ata, m2a[q], w, ata);
            FMA2(atb, m2b[q], w, atb);
        }
        float a0, a1;
        UNPK2(a0, a1, ata);
        float atta = sigf(a0 + a1 + s_ab);
        UNPK2(a0, a1, atb);
        float attb = sigf(a0 + a1 + s_ab);
        u64 pa, pb;
        PACK2(pa, atta, atta);
        PACK2(pb, attb, attb);
#pragma unroll
        for (int q = 0; q < 16; q++) {
            MUL2(m2a[q], m2a[q], pa);
            MUL2(m2b[q], m2b[q], pb);
        }
    }

    // ---- coord head, interleaved edges, OUTPUT-HALVED (16 hidden / pass):
    //      c2a[8]+c2b[8] u64 accums per pass -> 32 live regs instead of 64 ----
    float acca = 0.0f, accb = 0.0f;
#pragma unroll
    for (int hc = 0; hc < 2; hc++) {
        u64 c2a[8], c2b[8];
        const ulonglong2* cb = (const ulonglong2*)(s_misc + 96 + hc*16);
#pragma unroll
        for (int q = 0; q < 4; q++) {
            ulonglong2 v = cb[q];
            c2a[2*q] = v.x;  c2a[2*q+1] = v.y;
            c2b[2*q] = v.x;  c2b[2*q+1] = v.y;
        }
#pragma unroll 4
        for (int fp = 0; fp < 16; fp++) {
            float ma0, ma1, mb0, mb1;
            UNPK2(ma0, ma1, m2a[fp]);
            UNPK2(mb0, mb1, m2b[fp]);
            u64 pa0, pa1, pb0, pb1;
            PACK2(pa0, ma0, ma0); PACK2(pa1, ma1, ma1);
            PACK2(pb0, mb0, mb0); PACK2(pb1, mb1, mb1);
            // rows 2fp and 2fp+1, columns hc*16 .. hc*16+15
            const ulonglong2* wr0 = (const ulonglong2*)(s_c1 + (2*fp)*HH + hc*16);
            const ulonglong2* wr1 = (const ulonglong2*)(s_c1 + (2*fp+1)*HH + hc*16);
#pragma unroll
            for (int q = 0; q < 4; q++) {
                ulonglong2 wa = wr0[q], wb = wr1[q];
                FMA2(c2a[2*q],   pa0, wa.x, c2a[2*q]);
                FMA2(c2a[2*q+1], pa0, wa.y, c2a[2*q+1]);
                FMA2(c2a[2*q],   pa1, wb.x, c2a[2*q]);
                FMA2(c2a[2*q+1], pa1, wb.y, c2a[2*q+1]);
                FMA2(c2b[2*q],   pb0, wa.x, c2b[2*q]);
                FMA2(c2b[2*q+1], pb0, wa.y, c2b[2*q+1]);
                FMA2(c2b[2*q],   pb1, wb.x, c2b[2*q]);
                FMA2(c2b[2*q+1], pb1, wb.y, c2b[2*q+1]);
            }
        }
#pragma unroll
        for (int q = 0; q < 8; q++) {
            float c0, c1v;
            UNPK2(c0, c1v, c2a[q]);
            acca += siluf(c0)  * s_misc[160 + hc*16 + 2*q];
            acca += siluf(c1v) * s_misc[160 + hc*16 + 2*q + 1];
            UNPK2(c0, c1v, c2b[q]);
            accb += siluf(c0)  * s_misc[160 + hc*16 + 2*q];
            accb += siluf(c1v) * s_misc[160 + hc*16 + 2*q + 1];
        }
    }
    float transa = tanhf(acca);
    float transb = tanhf(accb);

    float valida = (j == i0) ? 0.0f : 1.0f;
    float validb = (j == i1) ? 0.0f : 1.0f;
    float coefa = valida * __fdividef(transa, da + 1.0f);
    float coefb = validb * __fdividef(transb, db + 1.0f);

    // ---- coord reductions (both edges) ----
    {
        float x0 = rxa*coefa, x1 = rya*coefa, x2 = rza*coefa;
        float y0 = rxb*coefb, y1 = ryb*coefb, y2 = rzb*coefb;
#pragma unroll
        for (int off = 16; off > 0; off >>= 1) {
            x0 += __shfl_xor_sync(0xffffffffu, x0, off);
            x1 += __shfl_xor_sync(0xffffffffu, x1, off);
            x2 += __shfl_xor_sync(0xffffffffu, x2, off);
            y0 += __shfl_xor_sync(0xffffffffu, y0, off);
            y1 += __shfl_xor_sync(0xffffffffu, y1, off);
            y2 += __shfl_xor_sync(0xffffffffu, y2, off);
        }
        if (lane == 0) {
            s_xp[0][warp][0] = x0; s_xp[0][warp][1] = x1; s_xp[0][warp][2] = x2;
            s_xp[1][warp][0] = y0; s_xp[1][warp][1] = y1; s_xp[1][warp][2] = y2;
        }
    }

    // ---- butterfly vector reduce of m over lanes, edge a then edge b ----
    {
        float mm[FF];
#pragma unroll
        for (int q = 0; q < 16; q++) UNPK2(mm[2*q], mm[2*q+1], m2a[q]);
#pragma unroll
        for (int f = 0; f < FF; f++) mm[f] *= valida;
#pragma unroll
        for (int off = 16, nh = 16; off > 0; off >>= 1, nh >>= 1) {
            bool hi = (lane & off);
#pragma unroll
            for (int tt = 0; tt < 16; tt++) {
                if (tt < nh) {
                    float kept = hi ? mm[nh + tt] : mm[tt];
                    float sent = hi ? mm[tt]      : mm[nh + tt];
                    float recv = __shfl_xor_sync(0xffffffffu, sent, off);
                    mm[tt] = kept + recv;
                }
            }
        }
        s_part[0][warp][lane] = mm[0];
#pragma unroll
        for (int q = 0; q < 16; q++) UNPK2(mm[2*q], mm[2*q+1], m2b[q]);
#pragma unroll
        for (int f = 0; f < FF; f++) mm[f] *= validb;
#pragma unroll
        for (int off = 16, nh = 16; off > 0; off >>= 1, nh >>= 1) {
            bool hi = (lane & off);
#pragma unroll
            for (int tt = 0; tt < 16; tt++) {
                if (tt < nh) {
                    float kept = hi ? mm[nh + tt] : mm[tt];
                    float sent = hi ? mm[tt]      : mm[nh + tt];
                    float recv = __shfl_xor_sync(0xffffffffu, sent, off);
                    mm[tt] = kept + recv;
                }
            }
        }
        s_part[1][warp][lane] = mm[0];
    }
    __syncthreads();

    // ---- tail: warp 0 -> node i0, warp 1 -> node i1 ----
    if (warp < 2) {
        int e = warp;
        int node = b*NP + i0 + e;
        int f = lane;
        if (f < 3) {
            float xs = s_xp[e][0][f] + s_xp[e][1][f] + s_xp[e][2][f] + s_xp[e][3][f];
            x_out[b*DIM + (i0+e)*ND + f] = s_xi[e][f] + xs * 5.0f;   // COORDS_RANGE
        }
        float mi = s_part[e][0][f] + s_part[e][1][f] + s_part[e][2][f] + s_part[e][3][f];
        float hv = h[node*FF + f];
        float acc = n_b1[f];
#pragma unroll
        for (int k = 0; k < FF; k++)
            acc += __shfl_sync(0xffffffffu, hv, k) * n_w1[k*HH + f];
#pragma unroll
        for (int k = 0; k < FF; k++)
            acc += __shfl_sync(0xffffffffu, mi, k) * n_w1[(FF + k)*HH + f];
        float tt2 = siluf(acc);
        float acc2 = n_b2[f];
#pragma unroll
        for (int k = 0; k < HH; k++)
            acc2 += __shfl_sync(0xffffffffu, tt2, k) * n_w2[k*FF + f];
        h_out[node*FF + f] = hv + acc2;
    }
}

// ---------------------------------------------------------------------------
extern "C" void kernel_launch(void* const* d_in, const int* in_sizes, int n_in,
                              void* d_out, int out_size)
{
    const float* x        = (const float*)d_in[0];
    const float* h        = (const float*)d_in[1];
    const float* d_static = (const float*)d_in[2];
    const float* e_w1     = (const float*)d_in[3];
    const float* e_b1     = (const float*)d_in[4];
    const float* e_w2     = (const float*)d_in[5];
    const float* e_b2     = (const float*)d_in[6];
    const float* n_w1     = (const float*)d_in[7];
    const float* n_b1     = (const float*)d_in[8];
    const float* n_w2     = (const float*)d_in[9];
    const float* n_b2     = (const float*)d_in[10];
    const float* c_w1     = (const float*)d_in[11];
    const float* c_b1     = (const float*)d_in[12];
    const float* c_w2     = (const float*)d_in[13];
    const float* a_w      = (const float*)d_in[14];
    const float* a_b      = (const float*)d_in[15];

    float* out   = (float*)d_out;
    float* x_out = out;                 // B*DIM floats
    float* h_out = out + BB*DIM;        // B*NP*FF floats

    prenode_kernel<<<NNODE/4, 128>>>(h, e_w1, e_b1);
    edge_kernel<<<BB*NP/2, 128>>>(x, d_static, e_w1, e_w2, e_b2,
                                  c_w1, c_b1, c_w2, a_w, a_b,
                                  h, n_w1, n_b1, n_w2, n_b2,
                                  x_out, h_out);
}

// round 10
// speedup vs baseline: 1.2480x; 1.2480x over previous
#include <cuda_runtime.h>
#include <math.h>

#define NP 128
#define ND 3
#define DIM (NP*ND)
#define FF 32
#define HH 32
#define BB 128
#define NEDGE (NP*(NP-1))   // 16256
#define NNODE (BB*NP)       // 16384
#define SBM 34              // padded Bm row stride (floats)
#define SRD 34              // padded m-spill row stride (floats)

// scratch (static device arrays, no allocation)
__device__ float g_A [NNODE*FF];   // h_i @ W_hi + e_b1
__device__ float g_Bm[NNODE*FF];   // h_j @ W_hj

// ---- packed f32x2 helpers (FFMA2 via PTX) ----
#define FMA2(d,a,b,c) asm("fma.rn.f32x2 %0, %1, %2, %3;" : "=l"(d) : "l"(a), "l"(b), "l"(c))
#define ADD2(d,a,b)   asm("add.rn.f32x2 %0, %1, %2;"     : "=l"(d) : "l"(a), "l"(b))
#define MUL2(d,a,b)   asm("mul.rn.f32x2 %0, %1, %2;"     : "=l"(d) : "l"(a), "l"(b))
#define PACK2(d,lo,hi) asm("mov.b64 %0, {%1, %2};" : "=l"(d) : "f"(lo), "f"(hi))
#define UNPK2(lo,hi,s) asm("mov.b64 {%0, %1}, %2;" : "=f"(lo), "=f"(hi) : "l"(s))

typedef unsigned long long u64;

__device__ __forceinline__ float sigf(float v) {
    return __fdividef(1.0f, 1.0f + __expf(-v));
}
__device__ __forceinline__ float siluf(float v) {
    return __fdividef(v, 1.0f + __expf(-v));
}

// ---------------------------------------------------------------------------
// Kernel 0: per-node precompute A = h@W_hi + e_b1, Bm = h@W_hj
// ---------------------------------------------------------------------------
__global__ __launch_bounds__(128) void prenode_kernel(
    const float* __restrict__ h, const float* __restrict__ e_w1,
    const float* __restrict__ e_b1)
{
    int node = blockIdx.x * 4 + (threadIdx.x >> 5);
    int f    = threadIdx.x & 31;
    float hv = h[node*FF + f];
    float a  = e_b1[f];
    float bm = 0.0f;
#pragma unroll
    for (int k = 0; k < FF; k++) {
        float hk = __shfl_sync(0xffffffffu, hv, k);
        a  += hk * e_w1[k*HH + f];
        bm += hk * e_w1[(FF + k)*HH + f];
    }
    g_A [node*FF + f] = a;
    g_Bm[node*FF + f] = bm;
}

// ---------------------------------------------------------------------------
// Kernel 1: fused edge + node kernel.
// Block = (b, 4 i's = 2 pairs). Thread j handles edges (i0->j),(i1->j) per pair.
// Edge-a's m spilled to smem (frees regs; doubles as the m_i reduce buffer);
// coord head output-halved. Target: <=128 regs, 4 blocks/SM.
// ---------------------------------------------------------------------------
__global__ __launch_bounds__(128, 4) void edge_kernel(
    const float* __restrict__ x,      const float* __restrict__ d_static,
    const float* __restrict__ e_w1,   const float* __restrict__ e_w2,
    const float* __restrict__ e_b2,   const float* __restrict__ c_w1,
    const float* __restrict__ c_b1,   const float* __restrict__ c_w2,
    const float* __restrict__ a_w,    const float* __restrict__ a_b,
    const float* __restrict__ h,
    const float* __restrict__ n_w1,   const float* __restrict__ n_b1,
    const float* __restrict__ n_w2,   const float* __restrict__ n_b2,
    float* __restrict__ x_out,        float* __restrict__ h_out)
{
    __shared__ __align__(16) float s_w2[FF*HH];     // e_w2
    __shared__ __align__(16) float s_c1[FF*HH];     // c_w1
    __shared__ __align__(16) float s_misc[10*32];   // wd,wds,eb2,cb1,aw,cw2,Ai0..Ai3
    __shared__ __align__(16) float s_bm[NP*SBM];    // staged Bm rows (batch b)
    __shared__ __align__(16) float s_red[NP*SRD];   // m spill / reduce buffer
    __shared__ float s_part[2][4][32];
    __shared__ float s_xp[2][4][3];
    __shared__ float s_xi[4][3];
    __shared__ float s_ab;

    const int t = threadIdx.x;
    const int b    = blockIdx.x >> 5;
    const int iblk = (blockIdx.x & 31) * 4;
    const int j = t;
    const int lane = t & 31;
    const int warp = t >> 5;

    for (int idx = t; idx < FF*HH; idx += 128) {
        s_w2[idx] = e_w2[idx];
        s_c1[idx] = c_w1[idx];
    }
    {   // coalesced stage of Bm for batch b (128 rows x 32 floats), stride SBM
        const float4* src = (const float4*)(g_Bm + b*NP*FF);
#pragma unroll
        for (int q = 0; q < 8; q++) {
            int idx = q*128 + t;
            int row = idx >> 3;
            int col = (idx & 7) * 4;
            float4 v = src[idx];
            s_bm[row*SBM + col + 0] = v.x;
            s_bm[row*SBM + col + 1] = v.y;
            s_bm[row*SBM + col + 2] = v.z;
            s_bm[row*SBM + col + 3] = v.w;
        }
    }
    if (t < 32) {
        s_misc[t      ] = e_w1[(2*FF    )*HH + t];  // w_d
        s_misc[32 + t ] = e_w1[(2*FF + 1)*HH + t];  // w_ds
        s_misc[64 + t ] = e_b2[t];
        s_misc[96 + t ] = c_b1[t];
        s_misc[128 + t] = a_w[t];
        s_misc[160 + t] = c_w2[t];
    }
    // A_i rows for the 4 i's
    s_misc[192 + t] = g_A[(b*NP + iblk + (t >> 5))*FF + (t & 31)];
    if (t == 0) s_ab = a_b[0];
    if (t < 12) s_xi[t/3][t%3] = x[b*DIM + (iblk + t/3)*ND + (t%3)];
    __syncthreads();

    // invariant per-thread loads
    const float xj0 = x[b*DIM + j*ND + 0];
    const float xj1 = x[b*DIM + j*ND + 1];
    const float xj2 = x[b*DIM + j*ND + 2];

    for (int p = 0; p < 2; p++) {
        const int i0 = iblk + 2*p, i1 = i0 + 1;

        // ---- geometry for both edges ----
        float rxa = s_xi[2*p][0]-xj0, rya = s_xi[2*p][1]-xj1, rza = s_xi[2*p][2]-xj2;
        float rxb = s_xi[2*p+1][0]-xj0, ryb = s_xi[2*p+1][1]-xj1, rzb = s_xi[2*p+1][2]-xj2;
        float d2a = rxa*rxa + rya*rya + rza*rza;
        float d2b = rxb*rxb + ryb*ryb + rzb*rzb;

        int ea = i0*(NP-1) + (j < i0 ? j : j-1); if (j == i0) ea = 0;
        int eb = i1*(NP-1) + (j < i1 ? j : j-1); if (j == i1) eb = 0;
        float dsa = d_static[b*NEDGE + ea];
        float dsb = d_static[b*NEDGE + eb];
        float ds2a = dsa*dsa, ds2b = dsb*dsb;

        u64 d2ap, ds2ap, d2bp, ds2bp;
        PACK2(d2ap, d2a, d2a);  PACK2(ds2ap, ds2a, ds2a);
        PACK2(d2bp, d2b, d2b);  PACK2(ds2bp, ds2b, ds2b);

        // ---- fused layer1->layer2 for both edges, weights loaded once ----
        u64 m2a[16], m2b[16];
        {
            const ulonglong2* bp = (const ulonglong2*)(s_misc + 64);
#pragma unroll
            for (int q = 0; q < 8; q++) {
                ulonglong2 v = bp[q];
                m2a[2*q] = v.x;  m2a[2*q+1] = v.y;
                m2b[2*q] = v.x;  m2b[2*q+1] = v.y;
            }
        }
        {
            const u64* Ai0p = (const u64*)(s_misc + 192 + p*64);
            const u64* Ai1p = (const u64*)(s_misc + 224 + p*64);
            const u64* Wd   = (const u64*)(s_misc + 0);
            const u64* Wds  = (const u64*)(s_misc + 32);
#pragma unroll 4
            for (int kp = 0; kp < 16; kp++) {
                u64 bm = *(const u64*)(s_bm + j*SBM + 2*kp);
                u64 wd = Wd[kp], ws = Wds[kp];
                u64 pa, pb;
                ADD2(pa, Ai0p[kp], bm);
                FMA2(pa, d2ap, wd, pa);
                FMA2(pa, ds2ap, ws, pa);
                ADD2(pb, Ai1p[kp], bm);
                FMA2(pb, d2bp, wd, pb);
                FMA2(pb, ds2bp, ws, pb);
                float va0, va1, vb0, vb1;
                UNPK2(va0, va1, pa);
                UNPK2(vb0, vb1, pb);
                va0 = siluf(va0); va1 = siluf(va1);
                vb0 = siluf(vb0); vb1 = siluf(vb1);
                u64 s0a, s1a, s0b, s1b;
                PACK2(s0a, va0, va0); PACK2(s1a, va1, va1);
                PACK2(s0b, vb0, vb0); PACK2(s1b, vb1, vb1);
                const ulonglong2* w0 = (const ulonglong2*)(s_w2 + (2*kp)*HH);
#pragma unroll
                for (int q = 0; q < 8; q++) {
                    ulonglong2 wa = w0[q], wb = w0[q+8];
                    FMA2(m2a[2*q],   s0a, wa.x, m2a[2*q]);
                    FMA2(m2a[2*q+1], s0a, wa.y, m2a[2*q+1]);
                    FMA2(m2a[2*q],   s1a, wb.x, m2a[2*q]);
                    FMA2(m2a[2*q+1], s1a, wb.y, m2a[2*q+1]);
                    FMA2(m2b[2*q],   s0b, wa.x, m2b[2*q]);
                    FMA2(m2b[2*q+1], s0b, wa.y, m2b[2*q+1]);
                    FMA2(m2b[2*q],   s1b, wb.x, m2b[2*q]);
                    FMA2(m2b[2*q+1], s1b, wb.y, m2b[2*q+1]);
                }
            }
        }

        // ---- silu on m (kept packed) ----
#pragma unroll
        for (int q = 0; q < 16; q++) {
            float v0, v1;
            UNPK2(v0, v1, m2a[q]); v0 = siluf(v0); v1 = siluf(v1); PACK2(m2a[q], v0, v1);
            UNPK2(v0, v1, m2b[q]); v0 = siluf(v0); v1 = siluf(v1); PACK2(m2b[q], v0, v1);
        }

        // ---- attention gates (packed dot) + validity mask folded in ----
        {
            const u64* awp = (const u64*)(s_misc + 128);
            u64 ata = 0ull, atb = 0ull;
#pragma unroll
            for (int q = 0; q < 16; q++) {
                u64 w = awp[q];
                FMA2(ata, m2a[q], w, ata);
                FMA2(atb, m2b[q], w, atb);
            }
            float a0, a1;
            UNPK2(a0, a1, ata);
            float atta = sigf(a0 + a1 + s_ab);
            UNPK2(a0, a1, atb);
            float attb = sigf(a0 + a1 + s_ab);
            if (j == i0) atta = 0.0f;      // mask diagonal edge a
            if (j == i1) attb = 0.0f;      // mask diagonal edge b
            u64 pa, pb;
            PACK2(pa, atta, atta);
            PACK2(pb, attb, attb);
#pragma unroll
            for (int q = 0; q < 16; q++) {
                MUL2(m2a[q], m2a[q], pa);
                MUL2(m2b[q], m2b[q], pb);
            }
        }

        // ---- spill masked m (edge a) to smem: frees m2a during coord head ----
#pragma unroll
        for (int q = 0; q < 16; q++)
            *(u64*)(s_red + j*SRD + 2*q) = m2a[q];
        __syncthreads();   // sync1: s_red(a) visible

        // ---- reduce-a: thread (f, q4) sums 32 j's of feature f ----
        {
            int f = t & 31, q4 = t >> 5;
            float acc = 0.0f;
            const float* base = s_red + (q4*32)*SRD + f;
#pragma unroll
            for (int n = 0; n < 32; n++) acc += base[n*SRD];
            s_part[0][q4][f] = acc;
        }

        // ---- coord head: interleaved edges, output-halved; edge-a m streamed
        //      from smem, edge-b m from regs ----
        float acca = 0.0f, accb = 0.0f;
#pragma unroll
        for (int hc = 0; hc < 2; hc++) {
            u64 c2a[8], c2b[8];
            const ulonglong2* cb = (const ulonglong2*)(s_misc + 96 + hc*16);
#pragma unroll
            for (int q = 0; q < 4; q++) {
                ulonglong2 v = cb[q];
                c2a[2*q] = v.x;  c2a[2*q+1] = v.y;
                c2b[2*q] = v.x;  c2b[2*q+1] = v.y;
            }
#pragma unroll 4
            for (int fp = 0; fp < 16; fp++) {
                u64 mav = *(const u64*)(s_red + j*SRD + 2*fp);
                float ma0, ma1, mb0, mb1;
                UNPK2(ma0, ma1, mav);
                UNPK2(mb0, mb1, m2b[fp]);
                u64 pa0, pa1, pb0, pb1;
                PACK2(pa0, ma0, ma0); PACK2(pa1, ma1, ma1);
                PACK2(pb0, mb0, mb0); PACK2(pb1, mb1, mb1);
                const ulonglong2* wr0 = (const ulonglong2*)(s_c1 + (2*fp)*HH + hc*16);
                const ulonglong2* wr1 = (const ulonglong2*)(s_c1 + (2*fp+1)*HH + hc*16);
#pragma unroll
                for (int q = 0; q < 4; q++) {
                    ulonglong2 wa = wr0[q], wb = wr1[q];
                    FMA2(c2a[2*q],   pa0, wa.x, c2a[2*q]);
                    FMA2(c2a[2*q+1], pa0, wa.y, c2a[2*q+1]);
                    FMA2(c2a[2*q],   pa1, wb.x, c2a[2*q]);
                    FMA2(c2a[2*q+1], pa1, wb.y, c2a[2*q+1]);
                    FMA2(c2b[2*q],   pb0, wa.x, c2b[2*q]);
                    FMA2(c2b[2*q+1], pb0, wa.y, c2b[2*q+1]);
                    FMA2(c2b[2*q],   pb1, wb.x, c2b[2*q]);
                    FMA2(c2b[2*q+1], pb1, wb.y, c2b[2*q+1]);
                }
            }
#pragma unroll
            for (int q = 0; q < 8; q++) {
                float c0, c1v;
                UNPK2(c0, c1v, c2a[q]);
                acca += siluf(c0)  * s_misc[160 + hc*16 + 2*q];
                acca += siluf(c1v) * s_misc[160 + hc*16 + 2*q + 1];
                UNPK2(c0, c1v, c2b[q]);
                accb += siluf(c0)  * s_misc[160 + hc*16 + 2*q];
                accb += siluf(c1v) * s_misc[160 + hc*16 + 2*q + 1];
            }
        }
        float transa = tanhf(acca);
        float transb = tanhf(accb);

        float valida = (j == i0) ? 0.0f : 1.0f;
        float validb = (j == i1) ? 0.0f : 1.0f;
        float da = sqrtf(d2a + 1e-6f);
        float db = sqrtf(d2b + 1e-6f);
        float coefa = valida * __fdividef(transa, da + 1.0f);
        float coefb = validb * __fdividef(transb, db + 1.0f);

        __syncthreads();   // sync2: all s_red(a) reads done

        // ---- spill masked m (edge b) and reduce-b ----
#pragma unroll
        for (int q = 0; q < 16; q++)
            *(u64*)(s_red + j*SRD + 2*q) = m2b[q];
        __syncthreads();   // sync3
        {
            int f = t & 31, q4 = t >> 5;
            float acc = 0.0f;
            const float* base = s_red + (q4*32)*SRD + f;
#pragma unroll
            for (int n = 0; n < 32; n++) acc += base[n*SRD];
            s_part[1][q4][f] = acc;
        }

        // ---- coord update reductions (both edges, warp butterfly) ----
        {
            float x0 = rxa*coefa, x1 = rya*coefa, x2 = rza*coefa;
            float y0 = rxb*coefb, y1 = ryb*coefb, y2 = rzb*coefb;
#pragma unroll
            for (int off = 16; off > 0; off >>= 1) {
                x0 += __shfl_xor_sync(0xffffffffu, x0, off);
                x1 += __shfl_xor_sync(0xffffffffu, x1, off);
                x2 += __shfl_xor_sync(0xffffffffu, x2, off);
                y0 += __shfl_xor_sync(0xffffffffu, y0, off);
                y1 += __shfl_xor_sync(0xffffffffu, y1, off);
                y2 += __shfl_xor_sync(0xffffffffu, y2, off);
            }
            if (lane == 0) {
                s_xp[0][warp][0] = x0; s_xp[0][warp][1] = x1; s_xp[0][warp][2] = x2;
                s_xp[1][warp][0] = y0; s_xp[1][warp][1] = y1; s_xp[1][warp][2] = y2;
            }
        }
        __syncthreads();   // sync4: s_part / s_xp ready

        // ---- tail: warp 0 -> node i0, warp 1 -> node i1 ----
        if (warp < 2) {
            int e = warp;
            int node = b*NP + i0 + e;
            int f = lane;
            if (f < 3) {
                float xs = s_xp[e][0][f] + s_xp[e][1][f] + s_xp[e][2][f] + s_xp[e][3][f];
                x_out[b*DIM + (i0+e)*ND + f] = s_xi[2*p+e][f] + xs * 5.0f;  // COORDS_RANGE
            }
            float mi = s_part[e][0][f] + s_part[e][1][f] + s_part[e][2][f] + s_part[e][3][f];
            float hv = h[node*FF + f];
            float acc = n_b1[f];
#pragma unroll
            for (int k = 0; k < FF; k++)
                acc += __shfl_sync(0xffffffffu, hv, k) * n_w1[k*HH + f];
#pragma unroll
            for (int k = 0; k < FF; k++)
                acc += __shfl_sync(0xffffffffu, mi, k) * n_w1[(FF + k)*HH + f];
            float tt2 = siluf(acc);
            float acc2 = n_b2[f];
#pragma unroll
            for (int k = 0; k < HH; k++)
                acc2 += __shfl_sync(0xffffffffu, tt2, k) * n_w2[k*FF + f];
            h_out[node*FF + f] = hv + acc2;
        }
    }
}

// ---------------------------------------------------------------------------
extern "C" void kernel_launch(void* const* d_in, const int* in_sizes, int n_in,
                              void* d_out, int out_size)
{
    const float* x        = (const float*)d_in[0];
    const float* h        = (const float*)d_in[1];
    const float* d_static = (const float*)d_in[2];
    const float* e_w1     = (const float*)d_in[3];
    const float* e_b1     = (const float*)d_in[4];
    const float* e_w2     = (const float*)d_in[5];
    const float* e_b2     = (const float*)d_in[6];
    const float* n_w1     = (const float*)d_in[7];
    const float* n_b1     = (const float*)d_in[8];
    const float* n_w2     = (const float*)d_in[9];
    const float* n_b2     = (const float*)d_in[10];
    const float* c_w1     = (const float*)d_in[11];
    const float* c_b1     = (const float*)d_in[12];
    const float* c_w2     = (const float*)d_in[13];
    const float* a_w      = (const float*)d_in[14];
    const float* a_b      = (const float*)d_in[15];

    float* out   = (float*)d_out;
    float* x_out = out;                 // B*DIM floats
    float* h_out = out + BB*DIM;        // B*NP*FF floats

    prenode_kernel<<<NNODE/4, 128>>>(h, e_w1, e_b1);
    edge_kernel<<<BB*NP/4, 128>>>(x, d_static, e_w1, e_w2, e_b2,
                                  c_w1, c_b1, c_w2, a_w, a_b,
                                  h, n_w1, n_b1, n_w2, n_b2,
                                  x_out, h_out);
}